// round 14
// baseline (speedup 1.0000x reference)
#include <cuda_runtime.h>
#include <cuda_bf16.h>
#include <cstdint>
#include <cstddef>

// Problem dims (fixed)
#define MDIM 8192   // B*S
#define DDIM 2048   // model dim
#define HDIM 8192   // hidden

// ---------------- device scratch ----------------
__device__ float          g_h  [(size_t)MDIM * HDIM];       // fp32 pre-activation; later reused for GEMM2 split-K partials
__device__ __nv_bfloat16  g_hq [(size_t)MDIM * HDIM];       // integer k in bf16
__device__ __nv_bfloat16  g_x  [(size_t)MDIM * 2 * DDIM];   // 2 bf16 splits [M][2*2048]
__device__ __nv_bfloat16  g_w1q[(size_t)DDIM * HDIM];       // q1 [D,H] = [K,N] N-contig
__device__ __nv_bfloat16  g_w2q[(size_t)HDIM * DDIM];       // q2^T [H,D] = [K,N] N-contig
__device__ float          g_xmax[MDIM];
__device__ double         g_part[2][1024];
__device__ float          g_scales[4];  // {s1, s2, s2/255, -}

// ---------------- helpers ----------------
__device__ __forceinline__ uint32_t cvta_smem(const void* p) {
    return (uint32_t)__cvta_generic_to_shared(p);
}
__device__ __forceinline__ void cp_async16(uint32_t dst, const void* src) {
    asm volatile("cp.async.cg.shared.global [%0], [%1], 16;\n" :: "r"(dst), "l"(src) : "memory");
}
__device__ __forceinline__ void ldsm_x4(uint32_t &r0, uint32_t &r1, uint32_t &r2, uint32_t &r3, uint32_t addr) {
    asm volatile("ldmatrix.sync.aligned.m8n8.x4.shared.b16 {%0,%1,%2,%3}, [%4];"
                 : "=r"(r0), "=r"(r1), "=r"(r2), "=r"(r3) : "r"(addr));
}
__device__ __forceinline__ void ldsm_x4_t(uint32_t &r0, uint32_t &r1, uint32_t &r2, uint32_t &r3, uint32_t addr) {
    asm volatile("ldmatrix.sync.aligned.m8n8.x4.trans.shared.b16 {%0,%1,%2,%3}, [%4];"
                 : "=r"(r0), "=r"(r1), "=r"(r2), "=r"(r3) : "r"(addr));
}
__device__ __forceinline__ void mma16816(float* c, const uint32_t* a, const uint32_t* b) {
    asm volatile("mma.sync.aligned.m16n8k16.row.col.f32.bf16.bf16.f32 "
                 "{%0,%1,%2,%3}, {%4,%5,%6,%7}, {%8,%9}, {%0,%1,%2,%3};"
                 : "+f"(c[0]), "+f"(c[1]), "+f"(c[2]), "+f"(c[3])
                 : "r"(a[0]), "r"(a[1]), "r"(a[2]), "r"(a[3]), "r"(b[0]), "r"(b[1]));
}

// ---------------- scale reduction (deterministic two-stage fp64) ----------------
__global__ void reduce_abs_partial(const float* __restrict__ a, const float* __restrict__ b,
                                   double* __restrict__ part, int n) {
    const float* src = blockIdx.y ? b : a;
    double* dst = part + (size_t)blockIdx.y * 1024;
    double s = 0.0;
    for (int i = blockIdx.x * 256 + threadIdx.x; i < n; i += 256 * 1024)
        s += (double)fabsf(src[i]);
    __shared__ double sm[256];
    sm[threadIdx.x] = s; __syncthreads();
    for (int t = 128; t > 0; t >>= 1) {
        if (threadIdx.x < t) sm[threadIdx.x] += sm[threadIdx.x + t];
        __syncthreads();
    }
    if (threadIdx.x == 0) dst[blockIdx.x] = sm[0];
}

__global__ void reduce_final(const double* __restrict__ part, float* __restrict__ scales, int n_elems) {
    __shared__ double sm[256];
    for (int y = 0; y < 2; y++) {
        double s = 0.0;
        for (int i = threadIdx.x; i < 1024; i += 256) s += part[(size_t)y * 1024 + i];
        sm[threadIdx.x] = s; __syncthreads();
        for (int t = 128; t > 0; t >>= 1) {
            if (threadIdx.x < t) sm[threadIdx.x] += sm[threadIdx.x + t];
            __syncthreads();
        }
        if (threadIdx.x == 0) {
            float sc = fmaxf((float)(sm[0] / (double)n_elems), 1e-5f);
            scales[y] = sc;
            if (y == 1) scales[2] = sc / 255.0f;
        }
        __syncthreads();
    }
}

// ---------------- fused prep (vectorized): x 2-split + quantize both weights ----------------
__device__ __forceinline__ uint32_t pack_bf2(float a, float b) {
    __nv_bfloat162 v = __floats2bfloat162_rn(a, b);
    return *reinterpret_cast<uint32_t*>(&v);
}

__global__ void prep(const float* __restrict__ x,
                     const float* __restrict__ c_fc,
                     const float* __restrict__ c_proj,
                     __nv_bfloat16* __restrict__ xs,
                     __nv_bfloat16* __restrict__ w1q,
                     __nv_bfloat16* __restrict__ w2q,
                     const float* __restrict__ scales) {
    const int tid = threadIdx.x;
    if (blockIdx.y == 0) {
        // x -> (hi, lo) bf16 splits; float4 in, 2x uint2 out
        int i = blockIdx.x * 256 + tid;            // float4 index
        float4 f = ((const float4*)x)[i];
        float h0 = __bfloat162float(__float2bfloat16(f.x));
        float h1 = __bfloat162float(__float2bfloat16(f.y));
        float h2 = __bfloat162float(__float2bfloat16(f.z));
        float h3 = __bfloat162float(__float2bfloat16(f.w));
        uint2 hi, lo;
        hi.x = pack_bf2(f.x, f.y);  hi.y = pack_bf2(f.z, f.w);
        lo.x = pack_bf2(f.x - h0, f.y - h1);
        lo.y = pack_bf2(f.z - h2, f.w - h3);
        int row = i >> 9;                           // 512 float4 per 2048-elem row
        int c4  = i & 511;
        uint2* dst = (uint2*)(xs + (size_t)row * 4096);
        dst[c4]       = hi;
        dst[c4 + 512] = lo;
    } else if (blockIdx.y == 1) {
        // quantize c_fc elementwise (layout kept [D,H])
        int i = blockIdx.x * 256 + tid;
        float s = scales[0];
        float4 w = ((const float4*)c_fc)[i];
        float q0 = fminf(fmaxf(rintf(w.x / s), -1.0f), 1.0f);
        float q1 = fminf(fmaxf(rintf(w.y / s), -1.0f), 1.0f);
        float q2 = fminf(fmaxf(rintf(w.z / s), -1.0f), 1.0f);
        float q3 = fminf(fmaxf(rintf(w.w / s), -1.0f), 1.0f);
        uint2 o; o.x = pack_bf2(q0, q1); o.y = pack_bf2(q2, q3);
        ((uint2*)w1q)[i] = o;
    } else {
        // transpose-quantize c_proj [D,H] -> [H,D]; 16384 tiles of 32x32
        __shared__ float tile[32][33];
        int h0 = (blockIdx.x & 255) * 32, d0 = (blockIdx.x >> 8) * 32;
        int tx = tid & 31, ty = tid >> 5;   // 32 x 8
        #pragma unroll
        for (int j = 0; j < 32; j += 8)
            tile[ty + j][tx] = c_proj[(size_t)(d0 + ty + j) * HDIM + h0 + tx];
        __syncthreads();
        float s = scales[1];
        #pragma unroll
        for (int j = 0; j < 32; j += 8) {
            float q = fminf(fmaxf(rintf(tile[tx][ty + j] / s), -1.0f), 1.0f);
            w2q[(size_t)(h0 + ty + j) * DDIM + d0 + tx] = __float2bfloat16(q);
        }
    }
}

// ---------------- relu^2 + rowmax + 8-bit requant (vectorized) ----------------
__global__ void act_quant(const float* __restrict__ h, __nv_bfloat16* __restrict__ hq,
                          float* __restrict__ xmax_out, const float* __restrict__ scales) {
    int row = blockIdx.x;
    int tid = threadIdx.x;
    const float s1 = scales[0];
    const float4* hr = (const float4*)(h + (size_t)row * HDIM);
    float4 pv[8];
    float lmax = 0.0f;
    #pragma unroll
    for (int i = 0; i < 8; i++) {
        float4 v = hr[tid + i * 256];
        float4 p;
        float t;
        t = s1 * v.x; p.x = (t > 0.0f) ? t * t : 0.0f;
        t = s1 * v.y; p.y = (t > 0.0f) ? t * t : 0.0f;
        t = s1 * v.z; p.z = (t > 0.0f) ? t * t : 0.0f;
        t = s1 * v.w; p.w = (t > 0.0f) ? t * t : 0.0f;
        pv[i] = p;
        lmax = fmaxf(lmax, fmaxf(fmaxf(p.x, p.y), fmaxf(p.z, p.w)));
    }
    __shared__ float red[256];
    red[tid] = lmax; __syncthreads();
    for (int t = 128; t > 0; t >>= 1) {
        if (tid < t) red[tid] = fmaxf(red[tid], red[tid + t]);
        __syncthreads();
    }
    float xm = fmaxf(red[0], 1e-5f);
    if (tid == 0) xmax_out[row] = xm;
    uint2* hqr = (uint2*)(hq + (size_t)row * HDIM);
    #pragma unroll
    for (int i = 0; i < 8; i++) {
        float4 p = pv[i];
        float k0 = rintf((p.x / xm) * 255.0f);
        float k1 = rintf((p.y / xm) * 255.0f);
        float k2 = rintf((p.z / xm) * 255.0f);
        float k3 = rintf((p.w / xm) * 255.0f);
        uint2 o; o.x = pack_bf2(k0, k1); o.y = pack_bf2(k2, k3);
        hqr[tid + i * 256] = o;
    }
}

// ---------------- split-K combine: out = (P0 + P1) * s2/255 * xmax[row] ----------------
__global__ void combine_scale(const float* __restrict__ P0, const float* __restrict__ P1,
                              float* __restrict__ out,
                              const float* __restrict__ scales,
                              const float* __restrict__ xmax) {
    int i = blockIdx.x * 256 + threadIdx.x;      // float4 index over M*D/4
    int row = i >> 9;                             // 512 float4 per 2048-col row
    float f = scales[2] * xmax[row];
    float4 a = ((const float4*)P0)[i];
    float4 b = ((const float4*)P1)[i];
    float4 o;
    o.x = (a.x + b.x) * f;
    o.y = (a.y + b.y) * f;
    o.z = (a.z + b.z) * f;
    o.w = (a.w + b.w) * f;
    ((float4*)out)[i] = o;
}

// =====================================================================
// bf16 GEMM: C[M,N] (per-z buffer) = fac * (A[M,K] @ B[K,N]); fp32 accum.
// A row-major (lda); B row-major N-contig (ldb), k-row wrap via mask.
// blockIdx.z selects a K-slice of KT k-chunks (absolute chunk = z*KT + kt)
// and an output buffer C + z*zstride (deterministic split-K).
// Tile 128x128xK64; 128 threads, 4 warps (2x2), warp tile 64x64.
// 3-stage cp.async ring, ONE __syncthreads per K=64 chunk, fragment
// double-buffering across kh. 2 independent CTAs/SM.
// =====================================================================
#define BM 128
#define BN 128
#define BK 64
#define A_ST 72    // elems; 144B pitch (bank stride 4 mod 32 -> conflict-free)
#define B_ST 136   // elems; 272B pitch (bank stride 4 mod 32 -> conflict-free)
#define A_BYTES (BM * A_ST * 2)          // 18432
#define B_BYTES (BK * B_ST * 2)          // 17408
#define STG_BYTES (A_BYTES + B_BYTES)    // 35840
#define NSTG 3

__global__ __launch_bounds__(128, 2) void gemm_bf16(
    const __nv_bfloat16* __restrict__ A, int lda,
    const __nv_bfloat16* __restrict__ B, int ldb, int browmask,
    float* __restrict__ C, int ldc, size_t zstride,
    int KT,
    const float* __restrict__ gscale,
    const float* __restrict__ rowscale)
{
    extern __shared__ __align__(16) char smem[];
    const int tid  = threadIdx.x;
    const int lane = tid & 31;
    const int wid  = tid >> 5;
    const int bm = blockIdx.y * BM;
    const int bn = blockIdx.x * BN;
    const int kt0 = blockIdx.z * KT;
    const int wm = (wid >> 1) * 64;   // 2 warp-rows
    const int wn = (wid & 1) * 64;    // 2 warp-cols
    float* Cz = C + (size_t)blockIdx.z * zstride;

    float acc[4][8][4];
    #pragma unroll
    for (int i = 0; i < 4; i++)
        #pragma unroll
        for (int j = 0; j < 8; j++)
            #pragma unroll
            for (int r = 0; r < 4; r++) acc[i][j][r] = 0.0f;

    auto load_tile = [&](int stg, int kt) {
        char* As = smem + stg * STG_BYTES;
        char* Bs = As + A_BYTES;
        const int k0 = (kt0 + kt) * BK;
        const int bk0 = k0 & browmask;
        #pragma unroll
        for (int i = 0; i < 8; i++) {   // A: 128x64 = 1024 x 16B chunks
            int idx = tid + 128 * i;
            int r = idx >> 3, c = (idx & 7) * 8;
            cp_async16(cvta_smem(As + (r * A_ST + c) * 2),
                       A + (size_t)(bm + r) * lda + k0 + c);
        }
        #pragma unroll
        for (int i = 0; i < 8; i++) {   // B: 64x128 = 1024 x 16B chunks
            int idx = tid + 128 * i;
            int r = idx >> 4, c = (idx & 15) * 8;
            cp_async16(cvta_smem(Bs + (r * B_ST + c) * 2),
                       B + (size_t)(bk0 + r) * ldb + bn + c);
        }
        asm volatile("cp.async.commit_group;\n" ::: "memory");
    };

    auto ldsm_frags = [&](uint32_t a_base, uint32_t b_base, int kh,
                          uint32_t (*afr)[4], uint32_t (*bfr)[2]) {
        #pragma unroll
        for (int im = 0; im < 4; im++) {
            int row = wm + im * 16 + (lane & 15);
            int col = kh * 16 + (lane >> 4) * 8;
            ldsm_x4(afr[im][0], afr[im][1], afr[im][2], afr[im][3],
                    a_base + (uint32_t)(row * A_ST + col) * 2u);
        }
        #pragma unroll
        for (int jp = 0; jp < 4; jp++) {
            int mtx  = lane >> 3;
            int krow = kh * 16 + (lane & 7) + (mtx & 1) * 8;
            int ncol = wn + jp * 16 + (mtx >> 1) * 8;
            uint32_t r0, r1, r2, r3;
            ldsm_x4_t(r0, r1, r2, r3, b_base + (uint32_t)(krow * B_ST + ncol) * 2u);
            bfr[jp * 2][0] = r0; bfr[jp * 2][1] = r1;
            bfr[jp * 2 + 1][0] = r2; bfr[jp * 2 + 1][1] = r3;
        }
    };

    load_tile(0, 0);
    load_tile(1, 1);

    uint32_t afr[2][4][4];
    uint32_t bfr[2][8][2];

    for (int kt = 0; kt < KT; kt++) {
        asm volatile("cp.async.wait_group 1;\n" ::: "memory");
        __syncthreads();

        const int stg = kt % NSTG;
        const uint32_t a_base = cvta_smem(smem + stg * STG_BYTES);
        const uint32_t b_base = a_base + A_BYTES;

        // critical-path fragment load FIRST, then issue next-stage DMA burst
        ldsm_frags(a_base, b_base, 0, afr[0], bfr[0]);
        if (kt + 2 < KT) load_tile((kt + 2) % NSTG, kt + 2);

        #pragma unroll
        for (int kh = 0; kh < 4; kh++) {
            const int cur = kh & 1;
            if (kh < 3) ldsm_frags(a_base, b_base, kh + 1, afr[cur ^ 1], bfr[cur ^ 1]);
            #pragma unroll
            for (int im = 0; im < 4; im++)
                #pragma unroll
                for (int jn = 0; jn < 8; jn++)
                    mma16816(acc[im][jn], afr[cur][im], bfr[cur][jn]);
        }
    }

    // epilogue
    float fac = gscale ? gscale[0] : 1.0f;
    const int g = lane >> 2, tg = lane & 3;
    #pragma unroll
    for (int im = 0; im < 4; im++) {
        int r0 = bm + wm + im * 16 + g;
        int r1 = r0 + 8;
        float f0 = fac, f1 = fac;
        if (rowscale) { f0 *= rowscale[r0]; f1 *= rowscale[r1]; }
        #pragma unroll
        for (int jn = 0; jn < 8; jn++) {
            int c = bn + wn + jn * 8 + tg * 2;
            float2* p0 = (float2*)(Cz + (size_t)r0 * ldc + c);
            float2* p1 = (float2*)(Cz + (size_t)r1 * ldc + c);
            float2 v0, v1;
            v0.x = acc[im][jn][0] * f0;  v0.y = acc[im][jn][1] * f0;
            v1.x = acc[im][jn][2] * f1;  v1.y = acc[im][jn][3] * f1;
            *p0 = v0; *p1 = v1;
        }
    }
}

// ---------------- host launcher ----------------
extern "C" void kernel_launch(void* const* d_in, const int* in_sizes, int n_in,
                              void* d_out, int out_size) {
    const float* x      = (const float*)d_in[0];
    const float* c_fc   = (const float*)d_in[1];
    const float* c_proj = (const float*)d_in[2];
    float* out = (float*)d_out;

    float *p_h, *p_xmax, *p_scales;
    double* p_part;
    __nv_bfloat16 *p_hq, *p_x, *p_w1q, *p_w2q;
    cudaGetSymbolAddress((void**)&p_h,      g_h);
    cudaGetSymbolAddress((void**)&p_hq,     g_hq);
    cudaGetSymbolAddress((void**)&p_x,      g_x);
    cudaGetSymbolAddress((void**)&p_w1q,    g_w1q);
    cudaGetSymbolAddress((void**)&p_w2q,    g_w2q);
    cudaGetSymbolAddress((void**)&p_xmax,   g_xmax);
    cudaGetSymbolAddress((void**)&p_part,   g_part);
    cudaGetSymbolAddress((void**)&p_scales, g_scales);

    const int n_w = DDIM * HDIM;
    const int SMEM_GEMM = NSTG * STG_BYTES;   // 107520

    cudaFuncSetAttribute(gemm_bf16, cudaFuncAttributeMaxDynamicSharedMemorySize, SMEM_GEMM);

    // (0,1) weight scales
    reduce_abs_partial<<<dim3(1024, 2), 256>>>(c_fc, c_proj, p_part, n_w);
    reduce_final<<<1, 256>>>(p_part, p_scales, n_w);

    // (2) fused prep (vectorized): x 2-split + both weight quantizations
    prep<<<dim3(16384, 3), 256>>>(x, c_fc, c_proj, p_x, p_w1q, p_w2q, p_scales);

    // (3) GEMM1 (fused 2-split via K-extension): h = xs[M,4096] @ q1-wrapped
    gemm_bf16<<<dim3(HDIM / BN, MDIM / BM, 1), 128, SMEM_GEMM>>>(
        p_x, 2 * DDIM, p_w1q, HDIM, DDIM - 1, p_h, HDIM, 0, 2 * DDIM / BK,
        nullptr, nullptr);

    // (4) relu^2 + rowmax + 8-bit requant (vectorized)
    act_quant<<<MDIM, 256>>>(p_h, p_hq, p_xmax, p_scales);

    // (5) GEMM2 split-K=2 into partials (g_h reused; exact integer math, any order identical)
    //     z=0 -> P0 = g_h[0 .. M*D), z=1 -> P1 = g_h[M*D .. 2*M*D)
    gemm_bf16<<<dim3(DDIM / BN, MDIM / BM, 2), 128, SMEM_GEMM>>>(
        p_hq, HDIM, p_w2q, DDIM, HDIM - 1, p_h, DDIM, (size_t)MDIM * DDIM,
        HDIM / BK / 2, nullptr, nullptr);

    // (6) combine partials + scale: out = (P0+P1) * s2/255 * xmax[m]
    combine_scale<<<MDIM * DDIM / 1024, 256>>>(p_h, p_h + (size_t)MDIM * DDIM, out,
                                               p_scales, p_xmax);
}

// round 15
// speedup vs baseline: 1.0214x; 1.0214x over previous
#include <cuda_runtime.h>
#include <cuda_bf16.h>
#include <cstdint>
#include <cstddef>

// Problem dims (fixed)
#define MDIM 8192   // B*S
#define DDIM 2048   // model dim
#define HDIM 8192   // hidden

// ---------------- device scratch ----------------
__device__ float          g_h  [(size_t)MDIM * HDIM];       // fp32 pre-activation
__device__ __nv_bfloat16  g_hq [(size_t)MDIM * HDIM];       // integer k in bf16
__device__ __nv_bfloat16  g_x  [(size_t)MDIM * 2 * DDIM];   // 2 bf16 splits [M][2*2048]
__device__ __nv_bfloat16  g_w1q[(size_t)DDIM * HDIM];       // q1 [D,H] = [K,N] N-contig
__device__ __nv_bfloat16  g_w2q[(size_t)HDIM * DDIM];       // q2^T [H,D] = [K,N] N-contig
__device__ float          g_xmax[MDIM];
__device__ double         g_part[2][1024];
__device__ float          g_scales[4];  // {s1, s2, s2/255, -}

// ---------------- helpers ----------------
__device__ __forceinline__ uint32_t cvta_smem(const void* p) {
    return (uint32_t)__cvta_generic_to_shared(p);
}
__device__ __forceinline__ void cp_async16(uint32_t dst, const void* src) {
    asm volatile("cp.async.cg.shared.global [%0], [%1], 16;\n" :: "r"(dst), "l"(src) : "memory");
}
__device__ __forceinline__ void ldsm_x4(uint32_t &r0, uint32_t &r1, uint32_t &r2, uint32_t &r3, uint32_t addr) {
    asm volatile("ldmatrix.sync.aligned.m8n8.x4.shared.b16 {%0,%1,%2,%3}, [%4];"
                 : "=r"(r0), "=r"(r1), "=r"(r2), "=r"(r3) : "r"(addr));
}
__device__ __forceinline__ void ldsm_x4_t(uint32_t &r0, uint32_t &r1, uint32_t &r2, uint32_t &r3, uint32_t addr) {
    asm volatile("ldmatrix.sync.aligned.m8n8.x4.trans.shared.b16 {%0,%1,%2,%3}, [%4];"
                 : "=r"(r0), "=r"(r1), "=r"(r2), "=r"(r3) : "r"(addr));
}
__device__ __forceinline__ void mma16816(float* c, const uint32_t* a, const uint32_t* b) {
    asm volatile("mma.sync.aligned.m16n8k16.row.col.f32.bf16.bf16.f32 "
                 "{%0,%1,%2,%3}, {%4,%5,%6,%7}, {%8,%9}, {%0,%1,%2,%3};"
                 : "+f"(c[0]), "+f"(c[1]), "+f"(c[2]), "+f"(c[3])
                 : "r"(a[0]), "r"(a[1]), "r"(a[2]), "r"(a[3]), "r"(b[0]), "r"(b[1]));
}

// ---------------- scale reduction (deterministic two-stage fp64) ----------------
__global__ void reduce_abs_partial(const float* __restrict__ a, const float* __restrict__ b,
                                   double* __restrict__ part, int n) {
    const float* src = blockIdx.y ? b : a;
    double* dst = part + (size_t)blockIdx.y * 1024;
    double s = 0.0;
    for (int i = blockIdx.x * 256 + threadIdx.x; i < n; i += 256 * 1024)
        s += (double)fabsf(src[i]);
    __shared__ double sm[256];
    sm[threadIdx.x] = s; __syncthreads();
    for (int t = 128; t > 0; t >>= 1) {
        if (threadIdx.x < t) sm[threadIdx.x] += sm[threadIdx.x + t];
        __syncthreads();
    }
    if (threadIdx.x == 0) dst[blockIdx.x] = sm[0];
}

__global__ void reduce_final(const double* __restrict__ part, float* __restrict__ scales, int n_elems) {
    __shared__ double sm[256];
    for (int y = 0; y < 2; y++) {
        double s = 0.0;
        for (int i = threadIdx.x; i < 1024; i += 256) s += part[(size_t)y * 1024 + i];
        sm[threadIdx.x] = s; __syncthreads();
        for (int t = 128; t > 0; t >>= 1) {
            if (threadIdx.x < t) sm[threadIdx.x] += sm[threadIdx.x + t];
            __syncthreads();
        }
        if (threadIdx.x == 0) {
            float sc = fmaxf((float)(sm[0] / (double)n_elems), 1e-5f);
            scales[y] = sc;
            if (y == 1) scales[2] = sc / 255.0f;
        }
        __syncthreads();
    }
}

// ---------------- fused prep (vectorized): x 2-split + quantize both weights ----------------
__device__ __forceinline__ uint32_t pack_bf2(float a, float b) {
    __nv_bfloat162 v = __floats2bfloat162_rn(a, b);
    return *reinterpret_cast<uint32_t*>(&v);
}

__global__ void prep(const float* __restrict__ x,
                     const float* __restrict__ c_fc,
                     const float* __restrict__ c_proj,
                     __nv_bfloat16* __restrict__ xs,
                     __nv_bfloat16* __restrict__ w1q,
                     __nv_bfloat16* __restrict__ w2q,
                     const float* __restrict__ scales) {
    const int tid = threadIdx.x;
    if (blockIdx.y == 0) {
        // x -> (hi, lo) bf16 splits; float4 in, 2x uint2 out
        int i = blockIdx.x * 256 + tid;            // float4 index
        float4 f = ((const float4*)x)[i];
        float h0 = __bfloat162float(__float2bfloat16(f.x));
        float h1 = __bfloat162float(__float2bfloat16(f.y));
        float h2 = __bfloat162float(__float2bfloat16(f.z));
        float h3 = __bfloat162float(__float2bfloat16(f.w));
        uint2 hi, lo;
        hi.x = pack_bf2(f.x, f.y);  hi.y = pack_bf2(f.z, f.w);
        lo.x = pack_bf2(f.x - h0, f.y - h1);
        lo.y = pack_bf2(f.z - h2, f.w - h3);
        int row = i >> 9;                           // 512 float4 per 2048-elem row
        int c4  = i & 511;
        uint2* dst = (uint2*)(xs + (size_t)row * 4096);
        dst[c4]       = hi;
        dst[c4 + 512] = lo;
    } else if (blockIdx.y == 1) {
        // quantize c_fc elementwise (layout kept [D,H])
        int i = blockIdx.x * 256 + tid;
        float s = scales[0];
        float4 w = ((const float4*)c_fc)[i];
        float q0 = fminf(fmaxf(rintf(w.x / s), -1.0f), 1.0f);
        float q1 = fminf(fmaxf(rintf(w.y / s), -1.0f), 1.0f);
        float q2 = fminf(fmaxf(rintf(w.z / s), -1.0f), 1.0f);
        float q3 = fminf(fmaxf(rintf(w.w / s), -1.0f), 1.0f);
        uint2 o; o.x = pack_bf2(q0, q1); o.y = pack_bf2(q2, q3);
        ((uint2*)w1q)[i] = o;
    } else {
        // transpose-quantize c_proj [D,H] -> [H,D]; 16384 tiles of 32x32
        __shared__ float tile[32][33];
        int h0 = (blockIdx.x & 255) * 32, d0 = (blockIdx.x >> 8) * 32;
        int tx = tid & 31, ty = tid >> 5;   // 32 x 8
        #pragma unroll
        for (int j = 0; j < 32; j += 8)
            tile[ty + j][tx] = c_proj[(size_t)(d0 + ty + j) * HDIM + h0 + tx];
        __syncthreads();
        float s = scales[1];
        #pragma unroll
        for (int j = 0; j < 32; j += 8) {
            float q = fminf(fmaxf(rintf(tile[tx][ty + j] / s), -1.0f), 1.0f);
            w2q[(size_t)(h0 + ty + j) * DDIM + d0 + tx] = __float2bfloat16(q);
        }
    }
}

// ---------------- relu^2 + rowmax + 8-bit requant (vectorized) ----------------
__global__ void act_quant(const float* __restrict__ h, __nv_bfloat16* __restrict__ hq,
                          float* __restrict__ xmax_out, const float* __restrict__ scales) {
    int row = blockIdx.x;
    int tid = threadIdx.x;
    const float s1 = scales[0];
    const float4* hr = (const float4*)(h + (size_t)row * HDIM);
    float4 pv[8];
    float lmax = 0.0f;
    #pragma unroll
    for (int i = 0; i < 8; i++) {
        float4 v = hr[tid + i * 256];
        float4 p;
        float t;
        t = s1 * v.x; p.x = (t > 0.0f) ? t * t : 0.0f;
        t = s1 * v.y; p.y = (t > 0.0f) ? t * t : 0.0f;
        t = s1 * v.z; p.z = (t > 0.0f) ? t * t : 0.0f;
        t = s1 * v.w; p.w = (t > 0.0f) ? t * t : 0.0f;
        pv[i] = p;
        lmax = fmaxf(lmax, fmaxf(fmaxf(p.x, p.y), fmaxf(p.z, p.w)));
    }
    __shared__ float red[256];
    red[tid] = lmax; __syncthreads();
    for (int t = 128; t > 0; t >>= 1) {
        if (tid < t) red[tid] = fmaxf(red[tid], red[tid + t]);
        __syncthreads();
    }
    float xm = fmaxf(red[0], 1e-5f);
    if (tid == 0) xmax_out[row] = xm;
    uint2* hqr = (uint2*)(hq + (size_t)row * HDIM);
    #pragma unroll
    for (int i = 0; i < 8; i++) {
        float4 p = pv[i];
        float k0 = rintf((p.x / xm) * 255.0f);
        float k1 = rintf((p.y / xm) * 255.0f);
        float k2 = rintf((p.z / xm) * 255.0f);
        float k3 = rintf((p.w / xm) * 255.0f);
        uint2 o; o.x = pack_bf2(k0, k1); o.y = pack_bf2(k2, k3);
        hqr[tid + i * 256] = o;
    }
}

// =====================================================================
// bf16 GEMM (templated on N-tile): C[M,N] = fac * (A[M,K] @ B[K,N]).
// A row-major (lda); B row-major N-contig (ldb), k-row wrap via mask.
// Tile 128xTBNxK64; 128 threads, 4 warps (2x2), warp tile 64x(TBN/2).
// 3-stage cp.async ring, ONE __syncthreads per K=64 chunk, fragment
// double-buffering across kh. 2 independent CTAs/SM.
// TBN=128 for GEMM1 (proven R13 config); TBN=64 for GEMM2 so its grid
// is 2048 CTAs -> 6.92 waves (1% tail) instead of 3.46 (13.5% tail).
// =====================================================================
#define BM 128
#define BK 64
#define A_ST 72    // elems; 144B pitch (bank stride 4 mod 32 -> conflict-free)
#define A_BYTES (BM * A_ST * 2)          // 18432
#define NSTG 3

template<int TBN>
__global__ __launch_bounds__(128, 2) void gemm_bf16(
    const __nv_bfloat16* __restrict__ A, int lda,
    const __nv_bfloat16* __restrict__ B, int ldb, int browmask,
    float* __restrict__ C, int ldc,
    int KT,
    const float* __restrict__ gscale,
    const float* __restrict__ rowscale)
{
    constexpr int B_ST = TBN + 8;                    // 136 or 72; 16B-aligned pitch, bank stride 4
    constexpr int B_BYTES = BK * B_ST * 2;           // 17408 or 9216
    constexpr int STG_BYTES = A_BYTES + B_BYTES;     // 35840 or 27648
    constexpr int WN_TILE = TBN / 2;                 // 64 or 32
    constexpr int NJP = WN_TILE / 16;                // 4 or 2 (ldsm_x4_t per kh)
    constexpr int NJN = WN_TILE / 8;                 // 8 or 4 (mma n-steps)
    constexpr int B_CHUNKS = BK * TBN / 8;           // 1024 or 512 (16B chunks)

    extern __shared__ __align__(16) char smem[];
    const int tid  = threadIdx.x;
    const int lane = tid & 31;
    const int wid  = tid >> 5;
    const int bm = blockIdx.y * BM;
    const int bn = blockIdx.x * TBN;
    const int wm = (wid >> 1) * 64;          // 2 warp-rows
    const int wn = (wid & 1) * WN_TILE;      // 2 warp-cols

    float acc[4][NJN][4];
    #pragma unroll
    for (int i = 0; i < 4; i++)
        #pragma unroll
        for (int j = 0; j < NJN; j++)
            #pragma unroll
            for (int r = 0; r < 4; r++) acc[i][j][r] = 0.0f;

    auto load_tile = [&](int stg, int kt) {
        char* As = smem + stg * STG_BYTES;
        char* Bs = As + A_BYTES;
        const int k0 = kt * BK;
        const int bk0 = k0 & browmask;
        #pragma unroll
        for (int i = 0; i < 8; i++) {   // A: 128x64 = 1024 x 16B chunks
            int idx = tid + 128 * i;
            int r = idx >> 3, c = (idx & 7) * 8;
            cp_async16(cvta_smem(As + (r * A_ST + c) * 2),
                       A + (size_t)(bm + r) * lda + k0 + c);
        }
        #pragma unroll
        for (int i = 0; i < B_CHUNKS / 128; i++) {   // B: 64xTBN 16B chunks
            int idx = tid + 128 * i;
            int r = idx / (TBN / 8), c = (idx % (TBN / 8)) * 8;
            cp_async16(cvta_smem(Bs + (r * B_ST + c) * 2),
                       B + (size_t)(bk0 + r) * ldb + bn + c);
        }
        asm volatile("cp.async.commit_group;\n" ::: "memory");
    };

    auto ldsm_frags = [&](uint32_t a_base, uint32_t b_base, int kh,
                          uint32_t (*afr)[4], uint32_t (*bfr)[2]) {
        #pragma unroll
        for (int im = 0; im < 4; im++) {
            int row = wm + im * 16 + (lane & 15);
            int col = kh * 16 + (lane >> 4) * 8;
            ldsm_x4(afr[im][0], afr[im][1], afr[im][2], afr[im][3],
                    a_base + (uint32_t)(row * A_ST + col) * 2u);
        }
        #pragma unroll
        for (int jp = 0; jp < NJP; jp++) {
            int mtx  = lane >> 3;
            int krow = kh * 16 + (lane & 7) + (mtx & 1) * 8;
            int ncol = wn + jp * 16 + (mtx >> 1) * 8;
            uint32_t r0, r1, r2, r3;
            ldsm_x4_t(r0, r1, r2, r3, b_base + (uint32_t)(krow * B_ST + ncol) * 2u);
            bfr[jp * 2][0] = r0; bfr[jp * 2][1] = r1;
            bfr[jp * 2 + 1][0] = r2; bfr[jp * 2 + 1][1] = r3;
        }
    };

    load_tile(0, 0);
    load_tile(1, 1);

    uint32_t afr[2][4][4];
    uint32_t bfr[2][NJN][2];

    for (int kt = 0; kt < KT; kt++) {
        asm volatile("cp.async.wait_group 1;\n" ::: "memory");
        __syncthreads();

        const int stg = kt % NSTG;
        const uint32_t a_base = cvta_smem(smem + stg * STG_BYTES);
        const uint32_t b_base = a_base + A_BYTES;

        // critical-path fragment load FIRST, then issue next-stage DMA burst
        ldsm_frags(a_base, b_base, 0, afr[0], bfr[0]);
        if (kt + 2 < KT) load_tile((kt + 2) % NSTG, kt + 2);

        #pragma unroll
        for (int kh = 0; kh < 4; kh++) {
            const int cur = kh & 1;
            if (kh < 3) ldsm_frags(a_base, b_base, kh + 1, afr[cur ^ 1], bfr[cur ^ 1]);
            #pragma unroll
            for (int im = 0; im < 4; im++)
                #pragma unroll
                for (int jn = 0; jn < NJN; jn++)
                    mma16816(acc[im][jn], afr[cur][im], bfr[cur][jn]);
        }
    }

    // epilogue
    float fac = gscale ? gscale[0] : 1.0f;
    const int g = lane >> 2, tg = lane & 3;
    #pragma unroll
    for (int im = 0; im < 4; im++) {
        int r0 = bm + wm + im * 16 + g;
        int r1 = r0 + 8;
        float f0 = fac, f1 = fac;
        if (rowscale) { f0 *= rowscale[r0]; f1 *= rowscale[r1]; }
        #pragma unroll
        for (int jn = 0; jn < NJN; jn++) {
            int c = bn + wn + jn * 8 + tg * 2;
            float2* p0 = (float2*)(C + (size_t)r0 * ldc + c);
            float2* p1 = (float2*)(C + (size_t)r1 * ldc + c);
            float2 v0, v1;
            v0.x = acc[im][jn][0] * f0;  v0.y = acc[im][jn][1] * f0;
            v1.x = acc[im][jn][2] * f1;  v1.y = acc[im][jn][3] * f1;
            *p0 = v0; *p1 = v1;
        }
    }
}

#define STG128 (A_BYTES + BK * (128 + 8) * 2)   // 35840
#define STG64  (A_BYTES + BK * (64 + 8) * 2)    // 27648

// ---------------- host launcher ----------------
extern "C" void kernel_launch(void* const* d_in, const int* in_sizes, int n_in,
                              void* d_out, int out_size) {
    const float* x      = (const float*)d_in[0];
    const float* c_fc   = (const float*)d_in[1];
    const float* c_proj = (const float*)d_in[2];
    float* out = (float*)d_out;

    float *p_h, *p_xmax, *p_scales;
    double* p_part;
    __nv_bfloat16 *p_hq, *p_x, *p_w1q, *p_w2q;
    cudaGetSymbolAddress((void**)&p_h,      g_h);
    cudaGetSymbolAddress((void**)&p_hq,     g_hq);
    cudaGetSymbolAddress((void**)&p_x,      g_x);
    cudaGetSymbolAddress((void**)&p_w1q,    g_w1q);
    cudaGetSymbolAddress((void**)&p_w2q,    g_w2q);
    cudaGetSymbolAddress((void**)&p_xmax,   g_xmax);
    cudaGetSymbolAddress((void**)&p_part,   g_part);
    cudaGetSymbolAddress((void**)&p_scales, g_scales);

    const int n_w = DDIM * HDIM;
    const int SMEM_G1 = NSTG * STG128;   // 107520
    const int SMEM_G2 = NSTG * STG64;    // 82944

    cudaFuncSetAttribute(gemm_bf16<128>, cudaFuncAttributeMaxDynamicSharedMemorySize, SMEM_G1);
    cudaFuncSetAttribute(gemm_bf16<64>,  cudaFuncAttributeMaxDynamicSharedMemorySize, SMEM_G2);

    // (0,1) weight scales
    reduce_abs_partial<<<dim3(1024, 2), 256>>>(c_fc, c_proj, p_part, n_w);
    reduce_final<<<1, 256>>>(p_part, p_scales, n_w);

    // (2) fused prep (vectorized): x 2-split + both weight quantizations
    prep<<<dim3(16384, 3), 256>>>(x, c_fc, c_proj, p_x, p_w1q, p_w2q, p_scales);

    // (3) GEMM1 (fused 2-split via K-extension): h = xs[M,4096] @ q1-wrapped
    gemm_bf16<128><<<dim3(HDIM / 128, MDIM / BM), 128, SMEM_G1>>>(
        p_x, 2 * DDIM, p_w1q, HDIM, DDIM - 1, p_h, HDIM, 2 * DDIM / BK,
        nullptr, nullptr);

    // (4) relu^2 + rowmax + 8-bit requant (vectorized)
    act_quant<<<MDIM, 256>>>(p_h, p_hq, p_xmax, p_scales);

    // (5) GEMM2 (BN=64 -> 2048 CTAs, ~1% wave tail): out = (hq @ q2^T) * s2/255 * xmax[m]
    gemm_bf16<64><<<dim3(DDIM / 64, MDIM / BM), 128, SMEM_G2>>>(
        p_hq, HDIM, p_w2q, DDIM, HDIM - 1, out, DDIM, HDIM / BK,
        p_scales + 2, p_xmax);
}

// round 16
// speedup vs baseline: 1.0360x; 1.0143x over previous
#include <cuda_runtime.h>
#include <cuda_bf16.h>
#include <cstdint>
#include <cstddef>

// Problem dims (fixed)
#define MDIM 8192   // B*S
#define DDIM 2048   // model dim
#define HDIM 8192   // hidden

// ---------------- device scratch ----------------
__device__ float          g_h  [(size_t)MDIM * HDIM];       // fp32 pre-activation
__device__ __nv_bfloat16  g_hq [(size_t)MDIM * HDIM];       // integer k in bf16
__device__ __nv_bfloat16  g_x  [(size_t)MDIM * 2 * DDIM];   // 2 bf16 splits [M][2*2048]
__device__ __nv_bfloat16  g_w1q[(size_t)HDIM * DDIM];       // q1^T [H,D] = [N,K] K-contig
__device__ __nv_bfloat16  g_w2q[(size_t)DDIM * HDIM];       // q2   [D,H] = [N,K] K-contig
__device__ float          g_xmax[MDIM];
__device__ double         g_part[2][1024];
__device__ float          g_scales[4];  // {s1, s2, s2/255, -}

// ---------------- helpers ----------------
__device__ __forceinline__ uint32_t cvta_smem(const void* p) {
    return (uint32_t)__cvta_generic_to_shared(p);
}
__device__ __forceinline__ void cp_async16(uint32_t dst, const void* src) {
    asm volatile("cp.async.cg.shared.global [%0], [%1], 16;\n" :: "r"(dst), "l"(src) : "memory");
}
__device__ __forceinline__ void ldsm_x4(uint32_t &r0, uint32_t &r1, uint32_t &r2, uint32_t &r3, uint32_t addr) {
    asm volatile("ldmatrix.sync.aligned.m8n8.x4.shared.b16 {%0,%1,%2,%3}, [%4];"
                 : "=r"(r0), "=r"(r1), "=r"(r2), "=r"(r3) : "r"(addr));
}
__device__ __forceinline__ void mma16816(float* c, const uint32_t* a, const uint32_t* b) {
    asm volatile("mma.sync.aligned.m16n8k16.row.col.f32.bf16.bf16.f32 "
                 "{%0,%1,%2,%3}, {%4,%5,%6,%7}, {%8,%9}, {%0,%1,%2,%3};"
                 : "+f"(c[0]), "+f"(c[1]), "+f"(c[2]), "+f"(c[3])
                 : "r"(a[0]), "r"(a[1]), "r"(a[2]), "r"(a[3]), "r"(b[0]), "r"(b[1]));
}

// ---------------- scale reduction (deterministic two-stage fp64, float4 loads) ----------------
__global__ void reduce_abs_partial(const float* __restrict__ a, const float* __restrict__ b,
                                   double* __restrict__ part, int n4) {
    const float4* src = (const float4*)(blockIdx.y ? b : a);
    double* dst = part + (size_t)blockIdx.y * 1024;
    double s = 0.0;
    for (int i = blockIdx.x * 256 + threadIdx.x; i < n4; i += 256 * 1024) {
        float4 v = src[i];
        s += (double)fabsf(v.x) + (double)fabsf(v.y) + (double)fabsf(v.z) + (double)fabsf(v.w);
    }
    __shared__ double sm[256];
    sm[threadIdx.x] = s; __syncthreads();
    for (int t = 128; t > 0; t >>= 1) {
        if (threadIdx.x < t) sm[threadIdx.x] += sm[threadIdx.x + t];
        __syncthreads();
    }
    if (threadIdx.x == 0) dst[blockIdx.x] = sm[0];
}

__global__ void reduce_final(const double* __restrict__ part, float* __restrict__ scales, int n_elems) {
    __shared__ double sm[256];
    for (int y = 0; y < 2; y++) {
        double s = 0.0;
        for (int i = threadIdx.x; i < 1024; i += 256) s += part[(size_t)y * 1024 + i];
        sm[threadIdx.x] = s; __syncthreads();
        for (int t = 128; t > 0; t >>= 1) {
            if (threadIdx.x < t) sm[threadIdx.x] += sm[threadIdx.x + t];
            __syncthreads();
        }
        if (threadIdx.x == 0) {
            float sc = fmaxf((float)(sm[0] / (double)n_elems), 1e-5f);
            scales[y] = sc;
            if (y == 1) scales[2] = sc / 255.0f;
        }
        __syncthreads();
    }
}

// ---------------- fused prep (vectorized): x 2-split + quantize both weights ----------------
__device__ __forceinline__ uint32_t pack_bf2(float a, float b) {
    __nv_bfloat162 v = __floats2bfloat162_rn(a, b);
    return *reinterpret_cast<uint32_t*>(&v);
}

__global__ void prep(const float* __restrict__ x,
                     const float* __restrict__ c_fc,
                     const float* __restrict__ c_proj,
                     __nv_bfloat16* __restrict__ xs,
                     __nv_bfloat16* __restrict__ w1q,
                     __nv_bfloat16* __restrict__ w2q,
                     const float* __restrict__ scales) {
    const int tid = threadIdx.x;
    if (blockIdx.y == 0) {
        // x -> (hi, lo) bf16 splits; float4 in, 2x uint2 out
        int i = blockIdx.x * 256 + tid;            // float4 index
        float4 f = ((const float4*)x)[i];
        float h0 = __bfloat162float(__float2bfloat16(f.x));
        float h1 = __bfloat162float(__float2bfloat16(f.y));
        float h2 = __bfloat162float(__float2bfloat16(f.z));
        float h3 = __bfloat162float(__float2bfloat16(f.w));
        uint2 hi, lo;
        hi.x = pack_bf2(f.x, f.y);  hi.y = pack_bf2(f.z, f.w);
        lo.x = pack_bf2(f.x - h0, f.y - h1);
        lo.y = pack_bf2(f.z - h2, f.w - h3);
        int row = i >> 9;                           // 512 float4 per 2048-elem row
        int c4  = i & 511;
        uint2* dst = (uint2*)(xs + (size_t)row * 4096);
        dst[c4]       = hi;
        dst[c4 + 512] = lo;
    } else if (blockIdx.y == 1) {
        // quantize c_proj elementwise (layout kept [D,H] = [N,K] K-contig for GEMM2)
        int i = blockIdx.x * 256 + tid;
        float s = scales[1];
        float4 w = ((const float4*)c_proj)[i];
        float q0 = fminf(fmaxf(rintf(w.x / s), -1.0f), 1.0f);
        float q1 = fminf(fmaxf(rintf(w.y / s), -1.0f), 1.0f);
        float q2 = fminf(fmaxf(rintf(w.z / s), -1.0f), 1.0f);
        float q3 = fminf(fmaxf(rintf(w.w / s), -1.0f), 1.0f);
        uint2 o; o.x = pack_bf2(q0, q1); o.y = pack_bf2(q2, q3);
        ((uint2*)w2q)[i] = o;
    } else {
        // transpose-quantize c_fc [D,H] -> w1q [H,D] (K-contig for GEMM1); 16384 tiles of 32x32
        __shared__ float tile[32][33];
        int h0 = (blockIdx.x & 255) * 32, d0 = (blockIdx.x >> 8) * 32;
        int tx = tid & 31, ty = tid >> 5;   // 32 x 8
        #pragma unroll
        for (int j = 0; j < 32; j += 8)
            tile[ty + j][tx] = c_fc[(size_t)(d0 + ty + j) * HDIM + h0 + tx];
        __syncthreads();
        float s = scales[0];
        #pragma unroll
        for (int j = 0; j < 32; j += 8) {
            float q = fminf(fmaxf(rintf(tile[tx][ty + j] / s), -1.0f), 1.0f);
            w1q[(size_t)(h0 + ty + j) * DDIM + d0 + tx] = __float2bfloat16(q);
        }
    }
}

// ---------------- relu^2 + rowmax + 8-bit requant (vectorized) ----------------
__global__ void act_quant(const float* __restrict__ h, __nv_bfloat16* __restrict__ hq,
                          float* __restrict__ xmax_out, const float* __restrict__ scales) {
    int row = blockIdx.x;
    int tid = threadIdx.x;
    const float s1 = scales[0];
    const float4* hr = (const float4*)(h + (size_t)row * HDIM);
    float4 pv[8];
    float lmax = 0.0f;
    #pragma unroll
    for (int i = 0; i < 8; i++) {
        float4 v = hr[tid + i * 256];
        float4 p;
        float t;
        t = s1 * v.x; p.x = (t > 0.0f) ? t * t : 0.0f;
        t = s1 * v.y; p.y = (t > 0.0f) ? t * t : 0.0f;
        t = s1 * v.z; p.z = (t > 0.0f) ? t * t : 0.0f;
        t = s1 * v.w; p.w = (t > 0.0f) ? t * t : 0.0f;
        pv[i] = p;
        lmax = fmaxf(lmax, fmaxf(fmaxf(p.x, p.y), fmaxf(p.z, p.w)));
    }
    __shared__ float red[256];
    red[tid] = lmax; __syncthreads();
    for (int t = 128; t > 0; t >>= 1) {
        if (tid < t) red[tid] = fmaxf(red[tid], red[tid + t]);
        __syncthreads();
    }
    float xm = fmaxf(red[0], 1e-5f);
    if (tid == 0) xmax_out[row] = xm;
    uint2* hqr = (uint2*)(hq + (size_t)row * HDIM);
    #pragma unroll
    for (int i = 0; i < 8; i++) {
        float4 p = pv[i];
        float k0 = rintf((p.x / xm) * 255.0f);
        float k1 = rintf((p.y / xm) * 255.0f);
        float k2 = rintf((p.z / xm) * 255.0f);
        float k3 = rintf((p.w / xm) * 255.0f);
        uint2 o; o.x = pack_bf2(k0, k1); o.y = pack_bf2(k2, k3);
        hqr[tid + i * 256] = o;
    }
}

// =====================================================================
// bf16 GEMM: C[M,N] = fac * (A[M,K] @ B[N,K]^T); fp32 accum.
// BOTH operands K-major: A row-major [M,K] (lda), B row-major [N,K]
// (ldb), k wrap via mask (K-extension). All ldsm are NON-trans.
// Tile 128x128xK64; 128 threads, 4 warps (2x2), warp tile 64x64.
// 3-stage cp.async ring, ONE __syncthreads per K=64 chunk, fragment
// double-buffering across kh. 2 independent CTAs/SM.
// =====================================================================
#define BM 128
#define BN 128
#define BK 64
#define A_ST 72    // elems; 144B pitch (16B phase stride covers all banks once)
#define B_ST 72    // same geometry as A
#define A_BYTES (BM * A_ST * 2)          // 18432
#define B_BYTES (BN * B_ST * 2)          // 18432
#define STG_BYTES (A_BYTES + B_BYTES)    // 36864
#define NSTG 3

__global__ __launch_bounds__(128, 2) void gemm_bf16(
    const __nv_bfloat16* __restrict__ A, int lda,
    const __nv_bfloat16* __restrict__ B, int ldb, int browmask,
    float* __restrict__ C, int ldc,
    int KT,
    const float* __restrict__ gscale,
    const float* __restrict__ rowscale)
{
    extern __shared__ __align__(16) char smem[];
    const int tid  = threadIdx.x;
    const int lane = tid & 31;
    const int wid  = tid >> 5;
    const int bm = blockIdx.y * BM;
    const int bn = blockIdx.x * BN;
    const int wm = (wid >> 1) * 64;   // 2 warp-rows
    const int wn = (wid & 1) * 64;    // 2 warp-cols

    float acc[4][8][4];
    #pragma unroll
    for (int i = 0; i < 4; i++)
        #pragma unroll
        for (int j = 0; j < 8; j++)
            #pragma unroll
            for (int r = 0; r < 4; r++) acc[i][j][r] = 0.0f;

    auto load_tile = [&](int stg, int kt) {
        char* As = smem + stg * STG_BYTES;
        char* Bs = As + A_BYTES;
        const int k0 = kt * BK;
        const int bk0 = k0 & browmask;
        #pragma unroll
        for (int i = 0; i < 8; i++) {   // A: 128 rows x 64 k = 1024 x 16B chunks
            int idx = tid + 128 * i;
            int r = idx >> 3, c = (idx & 7) * 8;
            cp_async16(cvta_smem(As + (r * A_ST + c) * 2),
                       A + (size_t)(bm + r) * lda + k0 + c);
        }
        #pragma unroll
        for (int i = 0; i < 8; i++) {   // B: 128 n-rows x 64 k = 1024 x 16B chunks
            int idx = tid + 128 * i;
            int r = idx >> 3, c = (idx & 7) * 8;
            cp_async16(cvta_smem(Bs + (r * B_ST + c) * 2),
                       B + (size_t)(bn + r) * ldb + bk0 + c);
        }
        asm volatile("cp.async.commit_group;\n" ::: "memory");
    };

    auto ldsm_frags = [&](uint32_t a_base, uint32_t b_base, int kh,
                          uint32_t (*afr)[4], uint32_t (*bfr)[2]) {
        #pragma unroll
        for (int im = 0; im < 4; im++) {
            int row = wm + im * 16 + (lane & 15);
            int col = kh * 16 + (lane >> 4) * 8;
            ldsm_x4(afr[im][0], afr[im][1], afr[im][2], afr[im][3],
                    a_base + (uint32_t)(row * A_ST + col) * 2u);
        }
        // B non-trans from [N,K]: mtx0=(n0,k0) mtx1=(n0,k8) mtx2=(n8,k0) mtx3=(n8,k8)
        #pragma unroll
        for (int jp = 0; jp < 4; jp++) {
            int mtx  = lane >> 3;
            int nrow = wn + jp * 16 + (mtx >> 1) * 8 + (lane & 7);
            int kcol = kh * 16 + (mtx & 1) * 8;
            uint32_t r0, r1, r2, r3;
            ldsm_x4(r0, r1, r2, r3, b_base + (uint32_t)(nrow * B_ST + kcol) * 2u);
            bfr[jp * 2][0] = r0; bfr[jp * 2][1] = r1;
            bfr[jp * 2 + 1][0] = r2; bfr[jp * 2 + 1][1] = r3;
        }
    };

    load_tile(0, 0);
    load_tile(1, 1);

    uint32_t afr[2][4][4];
    uint32_t bfr[2][8][2];

    for (int kt = 0; kt < KT; kt++) {
        asm volatile("cp.async.wait_group 1;\n" ::: "memory");
        __syncthreads();

        const int stg = kt % NSTG;
        const uint32_t a_base = cvta_smem(smem + stg * STG_BYTES);
        const uint32_t b_base = a_base + A_BYTES;

        // critical-path fragment load FIRST, then issue next-stage DMA burst
        ldsm_frags(a_base, b_base, 0, afr[0], bfr[0]);
        if (kt + 2 < KT) load_tile((kt + 2) % NSTG, kt + 2);

        #pragma unroll
        for (int kh = 0; kh < 4; kh++) {
            const int cur = kh & 1;
            if (kh < 3) ldsm_frags(a_base, b_base, kh + 1, afr[cur ^ 1], bfr[cur ^ 1]);
            #pragma unroll
            for (int im = 0; im < 4; im++)
                #pragma unroll
                for (int jn = 0; jn < 8; jn++)
                    mma16816(acc[im][jn], afr[cur][im], bfr[cur][jn]);
        }
    }

    // epilogue
    float fac = gscale ? gscale[0] : 1.0f;
    const int g = lane >> 2, tg = lane & 3;
    #pragma unroll
    for (int im = 0; im < 4; im++) {
        int r0 = bm + wm + im * 16 + g;
        int r1 = r0 + 8;
        float f0 = fac, f1 = fac;
        if (rowscale) { f0 *= rowscale[r0]; f1 *= rowscale[r1]; }
        #pragma unroll
        for (int jn = 0; jn < 8; jn++) {
            int c = bn + wn + jn * 8 + tg * 2;
            float2* p0 = (float2*)(C + (size_t)r0 * ldc + c);
            float2* p1 = (float2*)(C + (size_t)r1 * ldc + c);
            float2 v0, v1;
            v0.x = acc[im][jn][0] * f0;  v0.y = acc[im][jn][1] * f0;
            v1.x = acc[im][jn][2] * f1;  v1.y = acc[im][jn][3] * f1;
            *p0 = v0; *p1 = v1;
        }
    }
}

// ---------------- host launcher ----------------
extern "C" void kernel_launch(void* const* d_in, const int* in_sizes, int n_in,
                              void* d_out, int out_size) {
    const float* x      = (const float*)d_in[0];
    const float* c_fc   = (const float*)d_in[1];
    const float* c_proj = (const float*)d_in[2];
    float* out = (float*)d_out;

    float *p_h, *p_xmax, *p_scales;
    double* p_part;
    __nv_bfloat16 *p_hq, *p_x, *p_w1q, *p_w2q;
    cudaGetSymbolAddress((void**)&p_h,      g_h);
    cudaGetSymbolAddress((void**)&p_hq,     g_hq);
    cudaGetSymbolAddress((void**)&p_x,      g_x);
    cudaGetSymbolAddress((void**)&p_w1q,    g_w1q);
    cudaGetSymbolAddress((void**)&p_w2q,    g_w2q);
    cudaGetSymbolAddress((void**)&p_xmax,   g_xmax);
    cudaGetSymbolAddress((void**)&p_part,   g_part);
    cudaGetSymbolAddress((void**)&p_scales, g_scales);

    const int n_w = DDIM * HDIM;
    const int SMEM_GEMM = NSTG * STG_BYTES;   // 110592

    cudaFuncSetAttribute(gemm_bf16, cudaFuncAttributeMaxDynamicSharedMemorySize, SMEM_GEMM);

    // (0,1) weight scales (deterministic two-stage fp64)
    reduce_abs_partial<<<dim3(1024, 2), 256>>>(c_fc, c_proj, p_part, n_w / 4);
    reduce_final<<<1, 256>>>(p_part, p_scales, n_w);

    // (2) fused prep (vectorized): x 2-split + w2 elementwise + w1 transpose-pack
    prep<<<dim3(16384, 3), 256>>>(x, c_fc, c_proj, p_x, p_w1q, p_w2q, p_scales);

    // (3) GEMM1 (fused 2-split via K-extension): h = xs[M,4096] @ w1q[H,2048]^T (k wraps)
    gemm_bf16<<<dim3(HDIM / BN, MDIM / BM), 128, SMEM_GEMM>>>(
        p_x, 2 * DDIM, p_w1q, DDIM, DDIM - 1, p_h, HDIM, 2 * DDIM / BK,
        nullptr, nullptr);

    // (4) relu^2 + rowmax + 8-bit requant (vectorized)
    act_quant<<<MDIM, 256>>>(p_h, p_hq, p_xmax, p_scales);

    // (5) GEMM2: out = (hq[M,8192] @ w2q[D,8192]^T) * s2/255 * xmax[m]
    gemm_bf16<<<dim3(DDIM / BN, MDIM / BM), 128, SMEM_GEMM>>>(
        p_hq, HDIM, p_w2q, HDIM, HDIM - 1, out, DDIM, HDIM / BK,
        p_scales + 2, p_xmax);
}

// round 17
// speedup vs baseline: 1.0795x; 1.0419x over previous
#include <cuda_runtime.h>
#include <cuda_bf16.h>
#include <cstdint>
#include <cstddef>

// Problem dims (fixed)
#define MDIM 8192   // B*S
#define DDIM 2048   // model dim
#define HDIM 8192   // hidden

// ---------------- device scratch ----------------
__device__ float          g_h  [(size_t)MDIM * HDIM];       // fp32 pre-activation
__device__ __nv_bfloat16  g_hq [(size_t)MDIM * HDIM];       // integer k in bf16
__device__ __nv_bfloat16  g_x  [(size_t)MDIM * 2 * DDIM];   // 2 bf16 splits [M][hi 2048 | lo 2048]
__device__ __nv_bfloat16  g_w1q[(size_t)HDIM * DDIM];       // q1^T [H,D] = [N,K] K-contig
__device__ __nv_bfloat16  g_w2q[(size_t)DDIM * HDIM];       // q2   [D,H] = [N,K] K-contig
__device__ float          g_xmax[MDIM];
__device__ double         g_part[2][1024];
__device__ float          g_scales[4];  // {s1, s2, s2/255, -}

// ---------------- helpers ----------------
__device__ __forceinline__ uint32_t cvta_smem(const void* p) {
    return (uint32_t)__cvta_generic_to_shared(p);
}
__device__ __forceinline__ void cp_async16(uint32_t dst, const void* src) {
    asm volatile("cp.async.cg.shared.global [%0], [%1], 16;\n" :: "r"(dst), "l"(src) : "memory");
}
__device__ __forceinline__ void cp_commit() {
    asm volatile("cp.async.commit_group;\n" ::: "memory");
}
__device__ __forceinline__ void ldsm_x4(uint32_t &r0, uint32_t &r1, uint32_t &r2, uint32_t &r3, uint32_t addr) {
    asm volatile("ldmatrix.sync.aligned.m8n8.x4.shared.b16 {%0,%1,%2,%3}, [%4];"
                 : "=r"(r0), "=r"(r1), "=r"(r2), "=r"(r3) : "r"(addr));
}
__device__ __forceinline__ void mma16816(float* c, const uint32_t* a, const uint32_t* b) {
    asm volatile("mma.sync.aligned.m16n8k16.row.col.f32.bf16.bf16.f32 "
                 "{%0,%1,%2,%3}, {%4,%5,%6,%7}, {%8,%9}, {%0,%1,%2,%3};"
                 : "+f"(c[0]), "+f"(c[1]), "+f"(c[2]), "+f"(c[3])
                 : "r"(a[0]), "r"(a[1]), "r"(a[2]), "r"(a[3]), "r"(b[0]), "r"(b[1]));
}

// ---------------- scale reduction (deterministic two-stage fp64, float4 loads) ----------------
__global__ void reduce_abs_partial(const float* __restrict__ a, const float* __restrict__ b,
                                   double* __restrict__ part, int n4) {
    const float4* src = (const float4*)(blockIdx.y ? b : a);
    double* dst = part + (size_t)blockIdx.y * 1024;
    double s = 0.0;
    for (int i = blockIdx.x * 256 + threadIdx.x; i < n4; i += 256 * 1024) {
        float4 v = src[i];
        s += (double)fabsf(v.x) + (double)fabsf(v.y) + (double)fabsf(v.z) + (double)fabsf(v.w);
    }
    __shared__ double sm[256];
    sm[threadIdx.x] = s; __syncthreads();
    for (int t = 128; t > 0; t >>= 1) {
        if (threadIdx.x < t) sm[threadIdx.x] += sm[threadIdx.x + t];
        __syncthreads();
    }
    if (threadIdx.x == 0) dst[blockIdx.x] = sm[0];
}

__global__ void reduce_final(const double* __restrict__ part, float* __restrict__ scales, int n_elems) {
    __shared__ double sm[256];
    for (int y = 0; y < 2; y++) {
        double s = 0.0;
        for (int i = threadIdx.x; i < 1024; i += 256) s += part[(size_t)y * 1024 + i];
        sm[threadIdx.x] = s; __syncthreads();
        for (int t = 128; t > 0; t >>= 1) {
            if (threadIdx.x < t) sm[threadIdx.x] += sm[threadIdx.x + t];
            __syncthreads();
        }
        if (threadIdx.x == 0) {
            float sc = fmaxf((float)(sm[0] / (double)n_elems), 1e-5f);
            scales[y] = sc;
            if (y == 1) scales[2] = sc / 255.0f;
        }
        __syncthreads();
    }
}

// ---------------- fused prep (vectorized): x 2-split + quantize both weights ----------------
__device__ __forceinline__ uint32_t pack_bf2(float a, float b) {
    __nv_bfloat162 v = __floats2bfloat162_rn(a, b);
    return *reinterpret_cast<uint32_t*>(&v);
}

__global__ void prep(const float* __restrict__ x,
                     const float* __restrict__ c_fc,
                     const float* __restrict__ c_proj,
                     __nv_bfloat16* __restrict__ xs,
                     __nv_bfloat16* __restrict__ w1q,
                     __nv_bfloat16* __restrict__ w2q,
                     const float* __restrict__ scales) {
    const int tid = threadIdx.x;
    if (blockIdx.y == 0) {
        // x -> (hi, lo) bf16 splits; float4 in, 2x uint2 out
        int i = blockIdx.x * 256 + tid;
        float4 f = ((const float4*)x)[i];
        float h0 = __bfloat162float(__float2bfloat16(f.x));
        float h1 = __bfloat162float(__float2bfloat16(f.y));
        float h2 = __bfloat162float(__float2bfloat16(f.z));
        float h3 = __bfloat162float(__float2bfloat16(f.w));
        uint2 hi, lo;
        hi.x = pack_bf2(f.x, f.y);  hi.y = pack_bf2(f.z, f.w);
        lo.x = pack_bf2(f.x - h0, f.y - h1);
        lo.y = pack_bf2(f.z - h2, f.w - h3);
        int row = i >> 9;                           // 512 float4 per 2048-elem row
        int c4  = i & 511;
        uint2* dst = (uint2*)(xs + (size_t)row * 4096);
        dst[c4]       = hi;
        dst[c4 + 512] = lo;
    } else if (blockIdx.y == 1) {
        // quantize c_proj elementwise (layout kept [D,H] = [N,K] K-contig for GEMM2)
        int i = blockIdx.x * 256 + tid;
        float s = scales[1];
        float4 w = ((const float4*)c_proj)[i];
        float q0 = fminf(fmaxf(rintf(w.x / s), -1.0f), 1.0f);
        float q1 = fminf(fmaxf(rintf(w.y / s), -1.0f), 1.0f);
        float q2 = fminf(fmaxf(rintf(w.z / s), -1.0f), 1.0f);
        float q3 = fminf(fmaxf(rintf(w.w / s), -1.0f), 1.0f);
        uint2 o; o.x = pack_bf2(q0, q1); o.y = pack_bf2(q2, q3);
        ((uint2*)w2q)[i] = o;
    } else {
        // transpose-quantize c_fc [D,H] -> w1q [H,D] (K-contig for GEMM1); 16384 tiles of 32x32
        __shared__ float tile[32][33];
        int h0 = (blockIdx.x & 255) * 32, d0 = (blockIdx.x >> 8) * 32;
        int tx = tid & 31, ty = tid >> 5;   // 32 x 8
        #pragma unroll
        for (int j = 0; j < 32; j += 8)
            tile[ty + j][tx] = c_fc[(size_t)(d0 + ty + j) * HDIM + h0 + tx];
        __syncthreads();
        float s = scales[0];
        #pragma unroll
        for (int j = 0; j < 32; j += 8) {
            float q = fminf(fmaxf(rintf(tile[tx][ty + j] / s), -1.0f), 1.0f);
            w1q[(size_t)(h0 + ty + j) * DDIM + d0 + tx] = __float2bfloat16(q);
        }
    }
}

// ---------------- relu^2 + rowmax + 8-bit requant (vectorized) ----------------
__global__ void act_quant(const float* __restrict__ h, __nv_bfloat16* __restrict__ hq,
                          float* __restrict__ xmax_out, const float* __restrict__ scales) {
    int row = blockIdx.x;
    int tid = threadIdx.x;
    const float s1 = scales[0];
    const float4* hr = (const float4*)(h + (size_t)row * HDIM);
    float4 pv[8];
    float lmax = 0.0f;
    #pragma unroll
    for (int i = 0; i < 8; i++) {
        float4 v = hr[tid + i * 256];
        float4 p;
        float t;
        t = s1 * v.x; p.x = (t > 0.0f) ? t * t : 0.0f;
        t = s1 * v.y; p.y = (t > 0.0f) ? t * t : 0.0f;
        t = s1 * v.z; p.z = (t > 0.0f) ? t * t : 0.0f;
        t = s1 * v.w; p.w = (t > 0.0f) ? t * t : 0.0f;
        pv[i] = p;
        lmax = fmaxf(lmax, fmaxf(fmaxf(p.x, p.y), fmaxf(p.z, p.w)));
    }
    __shared__ float red[256];
    red[tid] = lmax; __syncthreads();
    for (int t = 128; t > 0; t >>= 1) {
        if (tid < t) red[tid] = fmaxf(red[tid], red[tid + t]);
        __syncthreads();
    }
    float xm = fmaxf(red[0], 1e-5f);
    if (tid == 0) xmax_out[row] = xm;
    uint2* hqr = (uint2*)(hq + (size_t)row * HDIM);
    #pragma unroll
    for (int i = 0; i < 8; i++) {
        float4 p = pv[i];
        float k0 = rintf((p.x / xm) * 255.0f);
        float k1 = rintf((p.y / xm) * 255.0f);
        float k2 = rintf((p.z / xm) * 255.0f);
        float k3 = rintf((p.w / xm) * 255.0f);
        uint2 o; o.x = pack_bf2(k0, k1); o.y = pack_bf2(k2, k3);
        hqr[tid + i * 256] = o;
    }
}

// ---------------- shared GEMM tile geometry ----------------
#define BM 128
#define BN 128
#define BK 64
#define A_ST 72    // elems; 144B pitch, conflict-free
#define B_ST 72
#define T_BYTES (BM * A_ST * 2)    // 18432 (A tile == B tile size)

// fragment loader shared by both GEMMs: A [M,K] non-trans, B [N,K] non-trans
__device__ __forceinline__ void ldsm_frags_nk(
    uint32_t a_base, uint32_t b_base, int kh, int wm, int wn, int lane,
    uint32_t (*afr)[4], uint32_t (*bfr)[2])
{
    #pragma unroll
    for (int im = 0; im < 4; im++) {
        int row = wm + im * 16 + (lane & 15);
        int col = kh * 16 + (lane >> 4) * 8;
        ldsm_x4(afr[im][0], afr[im][1], afr[im][2], afr[im][3],
                a_base + (uint32_t)(row * A_ST + col) * 2u);
    }
    #pragma unroll
    for (int jp = 0; jp < 4; jp++) {
        int mtx  = lane >> 3;
        int nrow = wn + jp * 16 + (mtx >> 1) * 8 + (lane & 7);
        int kcol = kh * 16 + (mtx & 1) * 8;
        uint32_t r0, r1, r2, r3;
        ldsm_x4(r0, r1, r2, r3, b_base + (uint32_t)(nrow * B_ST + kcol) * 2u);
        bfr[jp * 2][0] = r0; bfr[jp * 2][1] = r1;
        bfr[jp * 2 + 1][0] = r2; bfr[jp * 2 + 1][1] = r3;
    }
}

// =====================================================================
// GEMM1 (interleaved 2-split, B reused across splits):
// h[M,H] = xs_hi @ w1q^T + xs_lo @ w1q^T.
// iter kt: split s = kt&1, k-chunk j = kt>>1. A ring 3, B ring 3;
// B(j) loaded ONCE (on even prefetch targets), serves kt=2j and 2j+1.
// One (possibly empty) commit per iter keeps wait_group 1 exact.
// =====================================================================
#define NSTG 3

__global__ __launch_bounds__(128, 2) void gemm1_i(
    const __nv_bfloat16* __restrict__ A,   // xs [M, 4096]
    const __nv_bfloat16* __restrict__ B,   // w1q [H, 2048]
    float* __restrict__ C)                 // h [M, H]
{
    extern __shared__ __align__(16) char smem[];
    char* Abase = smem;
    char* Bbase = smem + NSTG * T_BYTES;
    const int tid  = threadIdx.x;
    const int lane = tid & 31;
    const int wid  = tid >> 5;
    const int bm = blockIdx.y * BM;
    const int bn = blockIdx.x * BN;
    const int wm = (wid >> 1) * 64;
    const int wn = (wid & 1) * 64;
    const int KT = 2 * DDIM / BK;   // 64

    float acc[4][8][4];
    #pragma unroll
    for (int i = 0; i < 4; i++)
        #pragma unroll
        for (int j = 0; j < 8; j++)
            #pragma unroll
            for (int r = 0; r < 4; r++) acc[i][j][r] = 0.0f;

    auto load_A = [&](int stg, int kt) {
        char* As = Abase + stg * T_BYTES;
        const int s = kt & 1, j = kt >> 1;
        const size_t koff = (size_t)s * 2048 + (size_t)j * 64;
        #pragma unroll
        for (int i = 0; i < 8; i++) {
            int idx = tid + 128 * i;
            int r = idx >> 3, c = (idx & 7) * 8;
            cp_async16(cvta_smem(As + (r * A_ST + c) * 2),
                       A + (size_t)(bm + r) * 4096 + koff + c);
        }
    };
    auto load_B = [&](int stg, int j) {
        char* Bs = Bbase + stg * T_BYTES;
        #pragma unroll
        for (int i = 0; i < 8; i++) {
            int idx = tid + 128 * i;
            int r = idx >> 3, c = (idx & 7) * 8;
            cp_async16(cvta_smem(Bs + (r * B_ST + c) * 2),
                       B + (size_t)(bn + r) * 2048 + (size_t)j * 64 + c);
        }
    };

    // prologue: group0 = A(0)+B(0); group1 = A(1)
    load_A(0, 0); load_B(0, 0); cp_commit();
    load_A(1, 1); cp_commit();

    uint32_t afr[2][4][4];
    uint32_t bfr[2][8][2];

    for (int kt = 0; kt < KT; kt++) {
        asm volatile("cp.async.wait_group 1;\n" ::: "memory");
        __syncthreads();

        const uint32_t a_base = cvta_smem(Abase + (kt % 3) * T_BYTES);
        const uint32_t b_base = cvta_smem(Bbase + ((kt >> 1) % 3) * T_BYTES);

        // critical-path fragment load first, then prefetch (one group per iter)
        ldsm_frags_nk(a_base, b_base, 0, wm, wn, lane, afr[0], bfr[0]);
        if (kt + 2 < KT) {
            load_A((kt + 2) % 3, kt + 2);
            if (((kt + 2) & 1) == 0) load_B(((kt + 2) >> 1) % 3, (kt + 2) >> 1);
        }
        cp_commit();

        #pragma unroll
        for (int kh = 0; kh < 4; kh++) {
            const int cur = kh & 1;
            if (kh < 3) ldsm_frags_nk(a_base, b_base, kh + 1, wm, wn, lane, afr[cur ^ 1], bfr[cur ^ 1]);
            #pragma unroll
            for (int im = 0; im < 4; im++)
                #pragma unroll
                for (int jn = 0; jn < 8; jn++)
                    mma16816(acc[im][jn], afr[cur][im], bfr[cur][jn]);
        }
    }

    // epilogue (plain fp32 store)
    const int g = lane >> 2, tg = lane & 3;
    #pragma unroll
    for (int im = 0; im < 4; im++) {
        int r0 = bm + wm + im * 16 + g;
        int r1 = r0 + 8;
        #pragma unroll
        for (int jn = 0; jn < 8; jn++) {
            int c = bn + wn + jn * 8 + tg * 2;
            float2* p0 = (float2*)(C + (size_t)r0 * HDIM + c);
            float2* p1 = (float2*)(C + (size_t)r1 * HDIM + c);
            float2 v0, v1;
            v0.x = acc[im][jn][0];  v0.y = acc[im][jn][1];
            v1.x = acc[im][jn][2];  v1.y = acc[im][jn][3];
            *p0 = v0; *p1 = v1;
        }
    }
}

// =====================================================================
// GEMM2: out[M,D] = fac * (hq[M,K] @ w2q[D,K]^T), K = 8192.
// R16 structure (both operands K-major, non-trans ldsm), unified
// A+B stages, one commit per iter (race-free wait_group invariant).
// =====================================================================
#define STG2_BYTES (2 * T_BYTES)   // 36864

__global__ __launch_bounds__(128, 2) void gemm2(
    const __nv_bfloat16* __restrict__ A,   // hq [M, 8192]
    const __nv_bfloat16* __restrict__ B,   // w2q [D, 8192]
    float* __restrict__ C,                 // out [M, D]
    const float* __restrict__ gscale,
    const float* __restrict__ rowscale)
{
    extern __shared__ __align__(16) char smem[];
    const int tid  = threadIdx.x;
    const int lane = tid & 31;
    const int wid  = tid >> 5;
    const int bm = blockIdx.y * BM;
    const int bn = blockIdx.x * BN;
    const int wm = (wid >> 1) * 64;
    const int wn = (wid & 1) * 64;
    const int KT = HDIM / BK;   // 128

    float acc[4][8][4];
    #pragma unroll
    for (int i = 0; i < 4; i++)
        #pragma unroll
        for (int j = 0; j < 8; j++)
            #pragma unroll
            for (int r = 0; r < 4; r++) acc[i][j][r] = 0.0f;

    auto load_tile = [&](int stg, int kt) {
        char* As = smem + stg * STG2_BYTES;
        char* Bs = As + T_BYTES;
        const size_t k0 = (size_t)kt * BK;
        #pragma unroll
        for (int i = 0; i < 8; i++) {
            int idx = tid + 128 * i;
            int r = idx >> 3, c = (idx & 7) * 8;
            cp_async16(cvta_smem(As + (r * A_ST + c) * 2),
                       A + (size_t)(bm + r) * HDIM + k0 + c);
        }
        #pragma unroll
        for (int i = 0; i < 8; i++) {
            int idx = tid + 128 * i;
            int r = idx >> 3, c = (idx & 7) * 8;
            cp_async16(cvta_smem(Bs + (r * B_ST + c) * 2),
                       B + (size_t)(bn + r) * HDIM + k0 + c);
        }
    };

    load_tile(0, 0); cp_commit();
    load_tile(1, 1); cp_commit();

    uint32_t afr[2][4][4];
    uint32_t bfr[2][8][2];

    for (int kt = 0; kt < KT; kt++) {
        asm volatile("cp.async.wait_group 1;\n" ::: "memory");
        __syncthreads();

        const uint32_t a_base = cvta_smem(smem + (kt % NSTG) * STG2_BYTES);
        const uint32_t b_base = a_base + T_BYTES;

        ldsm_frags_nk(a_base, b_base, 0, wm, wn, lane, afr[0], bfr[0]);
        if (kt + 2 < KT) load_tile((kt + 2) % NSTG, kt + 2);
        cp_commit();

        #pragma unroll
        for (int kh = 0; kh < 4; kh++) {
            const int cur = kh & 1;
            if (kh < 3) ldsm_frags_nk(a_base, b_base, kh + 1, wm, wn, lane, afr[cur ^ 1], bfr[cur ^ 1]);
            #pragma unroll
            for (int im = 0; im < 4; im++)
                #pragma unroll
                for (int jn = 0; jn < 8; jn++)
                    mma16816(acc[im][jn], afr[cur][im], bfr[cur][jn]);
        }
    }

    // epilogue with scales
    const float fac = gscale[0];
    const int g = lane >> 2, tg = lane & 3;
    #pragma unroll
    for (int im = 0; im < 4; im++) {
        int r0 = bm + wm + im * 16 + g;
        int r1 = r0 + 8;
        float f0 = fac * rowscale[r0];
        float f1 = fac * rowscale[r1];
        #pragma unroll
        for (int jn = 0; jn < 8; jn++) {
            int c = bn + wn + jn * 8 + tg * 2;
            float2* p0 = (float2*)(C + (size_t)r0 * DDIM + c);
            float2* p1 = (float2*)(C + (size_t)r1 * DDIM + c);
            float2 v0, v1;
            v0.x = acc[im][jn][0] * f0;  v0.y = acc[im][jn][1] * f0;
            v1.x = acc[im][jn][2] * f1;  v1.y = acc[im][jn][3] * f1;
            *p0 = v0; *p1 = v1;
        }
    }
}

// ---------------- host launcher ----------------
extern "C" void kernel_launch(void* const* d_in, const int* in_sizes, int n_in,
                              void* d_out, int out_size) {
    const float* x      = (const float*)d_in[0];
    const float* c_fc   = (const float*)d_in[1];
    const float* c_proj = (const float*)d_in[2];
    float* out = (float*)d_out;

    float *p_h, *p_xmax, *p_scales;
    double* p_part;
    __nv_bfloat16 *p_hq, *p_x, *p_w1q, *p_w2q;
    cudaGetSymbolAddress((void**)&p_h,      g_h);
    cudaGetSymbolAddress((void**)&p_hq,     g_hq);
    cudaGetSymbolAddress((void**)&p_x,      g_x);
    cudaGetSymbolAddress((void**)&p_w1q,    g_w1q);
    cudaGetSymbolAddress((void**)&p_w2q,    g_w2q);
    cudaGetSymbolAddress((void**)&p_xmax,   g_xmax);
    cudaGetSymbolAddress((void**)&p_part,   g_part);
    cudaGetSymbolAddress((void**)&p_scales, g_scales);

    const int n_w = DDIM * HDIM;
    const int SMEM_GEMM = NSTG * 2 * T_BYTES;   // 110592 (both kernels)

    cudaFuncSetAttribute(gemm1_i, cudaFuncAttributeMaxDynamicSharedMemorySize, SMEM_GEMM);
    cudaFuncSetAttribute(gemm2,   cudaFuncAttributeMaxDynamicSharedMemorySize, SMEM_GEMM);

    // (0,1) weight scales (deterministic two-stage fp64)
    reduce_abs_partial<<<dim3(1024, 2), 256>>>(c_fc, c_proj, p_part, n_w / 4);
    reduce_final<<<1, 256>>>(p_part, p_scales, n_w);

    // (2) fused prep (vectorized): x 2-split + w2 elementwise + w1 transpose-pack
    prep<<<dim3(16384, 3), 256>>>(x, c_fc, c_proj, p_x, p_w1q, p_w2q, p_scales);

    // (3) GEMM1 (interleaved split, B loaded once per k-chunk)
    gemm1_i<<<dim3(HDIM / BN, MDIM / BM), 128, SMEM_GEMM>>>(p_x, p_w1q, p_h);

    // (4) relu^2 + rowmax + 8-bit requant (vectorized)
    act_quant<<<MDIM, 256>>>(p_h, p_hq, p_xmax, p_scales);

    // (5) GEMM2: out = (hq @ w2q^T) * s2/255 * xmax[m]
    gemm2<<<dim3(DDIM / BN, MDIM / BM), 128, SMEM_GEMM>>>(p_hq, p_w2q, out,
                                                          p_scales + 2, p_xmax);
}